// round 15
// baseline (speedup 1.0000x reference)
#include <cuda_runtime.h>
#include <cuda_fp16.h>
#include <cstdint>

#define BATCH 2
#define LEN   256

__device__ uint32_t g_Wh[256*32];      // QKVG weights fp16x2 hi  [out 256][in pairs 32]
__device__ uint32_t g_Wl[256*32];      // fp16x2 residual

__device__ __forceinline__ float ex2(float x) {
    float r; asm("ex2.approx.f32 %0, %1;" : "=f"(r) : "f"(x)); return r;
}
__device__ __forceinline__ uint32_t h16x2(float hi, float lo) {
    uint32_t r; asm("cvt.rn.f16x2.f32 %0, %1, %2;" : "=r"(r) : "f"(hi), "f"(lo)); return r;
}
__device__ __forceinline__ void mma_f16(float* c, const uint32_t* a, const uint32_t* b) {
    asm("mma.sync.aligned.m16n8k16.row.col.f32.f16.f16.f32 "
        "{%0,%1,%2,%3},{%4,%5,%6,%7},{%8,%9},{%0,%1,%2,%3};"
        : "+f"(c[0]), "+f"(c[1]), "+f"(c[2]), "+f"(c[3])
        : "r"(a[0]), "r"(a[1]), "r"(a[2]), "r"(a[3]), "r"(b[0]), "r"(b[1]));
}
#define LDSM4(r, addr) \
    asm volatile("ldmatrix.sync.aligned.m8n8.x4.shared.b16 {%0,%1,%2,%3}, [%4];" \
        : "=r"((r)[0]), "=r"((r)[1]), "=r"((r)[2]), "=r"((r)[3]) : "r"(addr))
#define LDSM4T(r, addr) \
    asm volatile("ldmatrix.sync.aligned.m8n8.x4.trans.shared.b16 {%0,%1,%2,%3}, [%4];" \
        : "=r"((r)[0]), "=r"((r)[1]), "=r"((r)[2]), "=r"((r)[3]) : "r"(addr))

// ---------------------------------------------------------------------------
// Kernel 0: one-time weight split (QKVG -> fp16 hi + fp16 residual).
// ---------------------------------------------------------------------------
__global__ void __launch_bounds__(256) k_prep(
    const float* __restrict__ Wq, const float* __restrict__ Wk,
    const float* __restrict__ Wv, const float* __restrict__ Wg)
{
    const int idx = blockIdx.x * 256 + threadIdx.x;   // 0..8191
    const int m = idx >> 11, o = (idx >> 5) & 63, i2 = idx & 31;
    const float* W = (m == 0) ? Wq : (m == 1) ? Wk : (m == 2) ? Wv : Wg;
    float2 wv = *(const float2*)(W + o*64 + i2*2);
    uint32_t ph = h16x2(wv.y, wv.x);
    __half2 hp = *(__half2*)&ph;
    uint32_t pl = h16x2(wv.y - __half2float(hp.y), wv.x - __half2float(hp.x));
    g_Wh[idx] = ph; g_Wl[idx] = pl;
}

// ---------------------------------------------------------------------------
// Fused kernel.  Attention loop split into two head-pair passes (halves live
// accumulator state -> ~25 free regs) with explicit double-buffered K/V
// fragment prefetch.  Math bit-identical to R14 (order per head unchanged).
// SMEM: sA[256][36w] | sK | sV | sWh[256][36] | sWl | sWo[64][36]
// ---------------------------------------------------------------------------
#define SM_K   36864
#define SM_V   73728
#define SM_WH  110592
#define SM_WL  147456
#define SM_WO  184320
#define SMEMT  193536
#define QSCALE 0.3606737602222409f   /* 0.25 * log2(e) */

__global__ void __launch_bounds__(512, 1) k_fused(
    const float* __restrict__ z, const float* __restrict__ ln_scale,
    const float* __restrict__ ln_bias, const float* __restrict__ bg,
    const float* __restrict__ Wo, const float* __restrict__ bo,
    float* __restrict__ y)
{
    extern __shared__ char sm[];
    uint32_t* sA  = (uint32_t*)sm;               // zn fp16 [256][36w]
    uint32_t* sKp = (uint32_t*)(sm + SM_K);
    uint32_t* sVp = (uint32_t*)(sm + SM_V);
    uint32_t* sWh = (uint32_t*)(sm + SM_WH);
    uint32_t* sWl = (uint32_t*)(sm + SM_WL);
    uint32_t* sWo = (uint32_t*)(sm + SM_WO);
    uint32_t sb;
    asm("{ .reg .u64 t; cvta.to.shared.u64 t, %1; cvt.u32.u64 %0, t; }"
        : "=r"(sb) : "l"(sm));

    const int tid  = threadIdx.x;
    const int base = blockIdx.x * 256;           // global row base (b*L+l)*256

    // ---- stage weights ----
    for (int idx = tid; idx < 8192; idx += 512) {
        int O = idx >> 5, i2 = idx & 31;
        sWh[O*36 + i2] = g_Wh[idx];
        sWl[O*36 + i2] = g_Wl[idx];
    }
    for (int idx = tid; idx < 2048; idx += 512) {
        int n = idx >> 5, i2 = idx & 31;
        float2 wv = *(const float2*)(Wo + n*64 + i2*2);
        sWo[n*36 + i2] = h16x2(wv.y, wv.x);
    }

    // ---- LayerNorm: 2 threads per row (32 channels each) -> sA fp16 ----
    {
        const int r = tid >> 1, q = tid & 1;
        const float* zr = z + (size_t)(base + r)*64 + q*32;
        float4 zv[8];
        #pragma unroll
        for (int f = 0; f < 8; f++) zv[f] = ((const float4*)zr)[f];
        float s = 0.f, ss = 0.f;
        #pragma unroll
        for (int f = 0; f < 8; f++) {
            s  += zv[f].x + zv[f].y + zv[f].z + zv[f].w;
            ss += zv[f].x*zv[f].x + zv[f].y*zv[f].y
                + zv[f].z*zv[f].z + zv[f].w*zv[f].w;
        }
        s  += __shfl_xor_sync(0xffffffffu, s, 1);
        ss += __shfl_xor_sync(0xffffffffu, ss, 1);
        float mu  = s * (1.0f/64.0f);
        float var = ss * (1.0f/64.0f) - mu*mu;
        float rs  = rsqrtf(var + 1e-5f);
        #pragma unroll
        for (int f = 0; f < 8; f++) {
            float4 sc = ((const float4*)(ln_scale + q*32))[f];
            float4 bi = ((const float4*)(ln_bias  + q*32))[f];
            float v0 = (zv[f].x - mu)*rs*sc.x + bi.x;
            float v1 = (zv[f].y - mu)*rs*sc.y + bi.y;
            float v2 = (zv[f].z - mu)*rs*sc.z + bi.z;
            float v3 = (zv[f].w - mu)*rs*sc.w + bi.w;
            sA[r*36 + q*16 + f*2]     = h16x2(v1, v0);
            sA[r*36 + q*16 + f*2 + 1] = h16x2(v3, v2);
        }
    }
    __syncthreads();

    const int w = tid >> 5, lane = tid & 31;
    const int g = lane >> 2, t = lane & 3;
    const int lr = w*16 + g;                     // local rows lr, lr+8
    const int r0 = base + lr;                    // global rows
    const uint32_t frow = (lane & 15);           // ldmatrix row-lane
    const uint32_t fcol = (lane >> 4) << 4;      // +16B for second 8-ch group

    // ---- projections: warp w -> its 16 rows x 256 out channels ----
    uint32_t qa[4][4];    // QK A-frags per head (prescaled)
    uint32_t Gh[4][4];    // gate frags per head (fp16)
    {
        uint32_t af[4][4];
        {
            const int arow  = w*16 + frow;
            #pragma unroll
            for (int kt = 0; kt < 4; kt++)
                LDSM4(af[kt], sb + arow*144 + kt*32 + fcol);
        }

        #pragma unroll
        for (int jp = 0; jp < 16; jp++) {
            float acc[2][4];
            #pragma unroll
            for (int jj = 0; jj < 2; jj++)
                #pragma unroll
                for (int k = 0; k < 4; k++) acc[jj][k] = 0.f;

            const uint32_t wbase = (jp*16 + frow)*144 + fcol;
            #pragma unroll
            for (int kt = 0; kt < 4; kt++) {
                uint32_t wh[4], wl[4];
                LDSM4(wh, sb + SM_WH + wbase + kt*32);
                LDSM4(wl, sb + SM_WL + wbase + kt*32);
                uint32_t b0h[2] = {wh[0], wh[2]}, b1h[2] = {wh[1], wh[3]};
                uint32_t b0l[2] = {wl[0], wl[2]}, b1l[2] = {wl[1], wl[3]};
                mma_f16(acc[0], af[kt], b0h);
                mma_f16(acc[0], af[kt], b0l);
                mma_f16(acc[1], af[kt], b1h);
                mma_f16(acc[1], af[kt], b1l);
            }

            #pragma unroll
            for (int jj = 0; jj < 2; jj++) {
                const int j = jp*2 + jj;
                if (j < 8) {                         // Q -> register A-frags
                    const int h = j >> 1, part = j & 1;
                    qa[h][part*2]     = h16x2(QSCALE*acc[jj][1], QSCALE*acc[jj][0]);
                    qa[h][part*2 + 1] = h16x2(QSCALE*acc[jj][3], QSCALE*acc[jj][2]);
                } else if (j < 16) {                 // K -> smem
                    const int jx = j - 8;
                    sKp[lr*36 + jx*4 + t]     = h16x2(acc[jj][1], acc[jj][0]);
                    sKp[(lr+8)*36 + jx*4 + t] = h16x2(acc[jj][3], acc[jj][2]);
                } else if (j < 24) {                 // V -> smem
                    const int jx = j - 16;
                    sVp[lr*36 + jx*4 + t]     = h16x2(acc[jj][1], acc[jj][0]);
                    sVp[(lr+8)*36 + jx*4 + t] = h16x2(acc[jj][3], acc[jj][2]);
                } else {                             // gate -> register frags
                    const int jx = j - 24, h = jx >> 1, part = jx & 1;
                    float2 bg2 = *(const float2*)(bg + jx*8 + 2*t);
                    float g0 = 1.0f/(1.0f + ex2(-1.4426950408889634f*(acc[jj][0] + bg2.x)));
                    float g1 = 1.0f/(1.0f + ex2(-1.4426950408889634f*(acc[jj][1] + bg2.y)));
                    float g2 = 1.0f/(1.0f + ex2(-1.4426950408889634f*(acc[jj][2] + bg2.x)));
                    float g3 = 1.0f/(1.0f + ex2(-1.4426950408889634f*(acc[jj][3] + bg2.y)));
                    Gh[h][part*2]     = h16x2(g1, g0);
                    Gh[h][part*2 + 1] = h16x2(g3, g2);
                }
            }
        }
    }
    __syncthreads();

    // ---- attention: two head-pair passes, double-buffered prefetch ----
    uint32_t A[4][4];                            // packed epilogue frags
    const uint32_t bones[2] = {0x3C003C00u, 0x3C003C00u};
    const uint32_t vbase = sb + SM_V + frow*144 + fcol;
    const int krow0 = g*36 + t;

    #pragma unroll
    for (int hp = 0; hp < 2; hp++) {
        float o_[2][2][4];                       // [hh][nt][frag]
        float lacc[2][4];
        #pragma unroll
        for (int hh = 0; hh < 2; hh++) {
            #pragma unroll
            for (int k = 0; k < 4; k++) lacc[hh][k] = 0.f;
            #pragma unroll
            for (int nt = 0; nt < 2; nt++)
                #pragma unroll
                for (int k = 0; k < 4; k++) o_[hh][nt][k] = 0.f;
        }

        // prefetch it=0  (it = kb*2 + hh, h = hp*2 + hh)
        uint32_t ckf[4], cvf[4];
        {
            const uint32_t* kp = sKp + krow0 + (hp*2)*8;
            ckf[0] = kp[0];      ckf[1] = kp[4];
            ckf[2] = kp[8*36];   ckf[3] = kp[8*36 + 4];
            LDSM4T(cvf, vbase + (hp*2)*32);
        }

        #pragma unroll
        for (int it = 0; it < 32; it++) {
            const int hh = it & 1;
            const int h  = hp*2 + hh;

            uint32_t nkf[4], nvf[4];
            if (it < 31) {                       // prefetch it+1
                const int nit = it + 1;
                const int nkb = nit >> 1, nh = hp*2 + (nit & 1);
                const uint32_t* kp = sKp + nkb*16*36 + krow0 + nh*8;
                nkf[0] = kp[0];      nkf[1] = kp[4];
                nkf[2] = kp[8*36];   nkf[3] = kp[8*36 + 4];
                LDSM4T(nvf, vbase + nkb*2304 + nh*32);
            }

            uint32_t kfa[2] = {ckf[0], ckf[1]};
            uint32_t kfb[2] = {ckf[2], ckf[3]};
            float s0[4] = {0.f,0.f,0.f,0.f}, s1[4] = {0.f,0.f,0.f,0.f};
            mma_f16(s0, qa[h], kfa);
            mma_f16(s1, qa[h], kfb);
            s0[0] = ex2(s0[0]); s0[1] = ex2(s0[1]);
            s0[2] = ex2(s0[2]); s0[3] = ex2(s0[3]);
            s1[0] = ex2(s1[0]); s1[1] = ex2(s1[1]);
            s1[2] = ex2(s1[2]); s1[3] = ex2(s1[3]);
            uint32_t pa[4];
            pa[0] = h16x2(s0[1], s0[0]);
            pa[1] = h16x2(s0[3], s0[2]);
            pa[2] = h16x2(s1[1], s1[0]);
            pa[3] = h16x2(s1[3], s1[2]);
            mma_f16(lacc[hh], pa, bones);
            mma_f16(o_[hh][0], pa, cvf + 0);
            mma_f16(o_[hh][1], pa, cvf + 2);

            if (it < 31) {
                ckf[0] = nkf[0]; ckf[1] = nkf[1];
                ckf[2] = nkf[2]; ckf[3] = nkf[3];
                cvf[0] = nvf[0]; cvf[1] = nvf[1];
                cvf[2] = nvf[2]; cvf[3] = nvf[3];
            }
        }

        // consume this pass's accumulators: normalize + gate -> A[h]
        #pragma unroll
        for (int hh = 0; hh < 2; hh++) {
            const int h = hp*2 + hh;
            const float inv0 = 1.0f / lacc[hh][0];   // row g
            const float inv1 = 1.0f / lacc[hh][2];   // row g+8
            #pragma unroll
            for (int nt = 0; nt < 2; nt++) {
                float2 G0 = __half22float2(*(__half2*)&Gh[h][nt*2]);
                float2 G1 = __half22float2(*(__half2*)&Gh[h][nt*2 + 1]);
                float v0 = o_[hh][nt][0]*inv0*G0.x;
                float v1 = o_[hh][nt][1]*inv0*G0.y;
                float v2 = o_[hh][nt][2]*inv1*G1.x;
                float v3 = o_[hh][nt][3]*inv1*G1.y;
                A[h][nt*2]     = h16x2(v1, v0);
                A[h][nt*2 + 1] = h16x2(v3, v2);
            }
        }
    }

    // ---- fused output projection (Wo frags via ldmatrix) ----
    #pragma unroll
    for (int jp = 0; jp < 4; jp++) {
        float acc[2][4];
        #pragma unroll
        for (int jj = 0; jj < 2; jj++)
            #pragma unroll
            for (int k = 0; k < 4; k++) acc[jj][k] = 0.f;

        const uint32_t wbase = (jp*16 + frow)*144 + fcol;
        #pragma unroll
        for (int h = 0; h < 4; h++) {
            uint32_t wm[4];
            LDSM4(wm, sb + SM_WO + wbase + h*32);
            uint32_t b0[2] = {wm[0], wm[2]}, b1[2] = {wm[1], wm[3]};
            mma_f16(acc[0], A[h], b0);
            mma_f16(acc[1], A[h], b1);
        }
        #pragma unroll
        for (int jj = 0; jj < 2; jj++) {
            const int c = (jp*2 + jj)*8 + 2*t;
            float2 bo2 = *(const float2*)(bo + c);
            *(float2*)(y + (size_t)r0*64 + c)     = make_float2(acc[jj][0]+bo2.x, acc[jj][1]+bo2.y);
            *(float2*)(y + (size_t)(r0+8)*64 + c) = make_float2(acc[jj][2]+bo2.x, acc[jj][3]+bo2.y);
        }
    }
}

// ---------------------------------------------------------------------------
extern "C" void kernel_launch(void* const* d_in, const int* in_sizes, int n_in,
                              void* d_out, int out_size)
{
    (void)in_sizes; (void)n_in; (void)out_size;
    const float* z  = (const float*)d_in[0];
    const float* ls = (const float*)d_in[1];
    const float* lb = (const float*)d_in[2];
    const float* Wq = (const float*)d_in[3];
    const float* Wk = (const float*)d_in[4];
    const float* Wv = (const float*)d_in[5];
    const float* Wg = (const float*)d_in[6];
    const float* bg = (const float*)d_in[7];
    const float* Wo = (const float*)d_in[8];
    const float* bo = (const float*)d_in[9];
    float* y = (float*)d_out;

    (void)cudaFuncSetAttribute(k_fused, cudaFuncAttributeMaxDynamicSharedMemorySize, SMEMT);

    k_prep<<<32, 256>>>(Wq, Wk, Wv, Wg);
    k_fused<<<BATCH*LEN, 512, SMEMT>>>(z, ls, lb, bg, Wo, bo, y);
}

// round 16
// speedup vs baseline: 1.1160x; 1.1160x over previous
#include <cuda_runtime.h>
#include <cuda_fp16.h>
#include <cstdint>

#define BATCH 2
#define LEN   256

__device__ uint32_t g_Wh[256*32];      // QKVG weights fp16x2  [out 256][in pairs 32]

__device__ __forceinline__ float ex2(float x) {
    float r; asm("ex2.approx.f32 %0, %1;" : "=f"(r) : "f"(x)); return r;
}
__device__ __forceinline__ uint32_t h16x2(float hi, float lo) {
    uint32_t r; asm("cvt.rn.f16x2.f32 %0, %1, %2;" : "=r"(r) : "f"(hi), "f"(lo)); return r;
}
__device__ __forceinline__ void mma_f16(float* c, const uint32_t* a, const uint32_t* b) {
    asm("mma.sync.aligned.m16n8k16.row.col.f32.f16.f16.f32 "
        "{%0,%1,%2,%3},{%4,%5,%6,%7},{%8,%9},{%0,%1,%2,%3};"
        : "+f"(c[0]), "+f"(c[1]), "+f"(c[2]), "+f"(c[3])
        : "r"(a[0]), "r"(a[1]), "r"(a[2]), "r"(a[3]), "r"(b[0]), "r"(b[1]));
}
#define LDSM4(r, addr) \
    asm volatile("ldmatrix.sync.aligned.m8n8.x4.shared.b16 {%0,%1,%2,%3}, [%4];" \
        : "=r"((r)[0]), "=r"((r)[1]), "=r"((r)[2]), "=r"((r)[3]) : "r"(addr))
#define LDSM4T(r, addr) \
    asm volatile("ldmatrix.sync.aligned.m8n8.x4.trans.shared.b16 {%0,%1,%2,%3}, [%4];" \
        : "=r"((r)[0]), "=r"((r)[1]), "=r"((r)[2]), "=r"((r)[3]) : "r"(addr))

// ---------------------------------------------------------------------------
// Kernel 0: one-time weight pack (QKVG -> fp16x2).
// ---------------------------------------------------------------------------
__global__ void __launch_bounds__(256) k_prep(
    const float* __restrict__ Wq, const float* __restrict__ Wk,
    const float* __restrict__ Wv, const float* __restrict__ Wg)
{
    const int idx = blockIdx.x * 256 + threadIdx.x;   // 0..8191
    const int m = idx >> 11, o = (idx >> 5) & 63, i2 = idx & 31;
    const float* W = (m == 0) ? Wq : (m == 1) ? Wk : (m == 2) ? Wv : Wg;
    float2 wv = *(const float2*)(W + o*64 + i2*2);
    g_Wh[idx] = h16x2(wv.y, wv.x);
}

// ---------------------------------------------------------------------------
// Fused kernel (R14 structure, single-fp16 projection weights — no lo
// residual: its outputs are rounded to fp16 anyway, added err ~4e-4 rms).
// SMEM: sA[256][36w] | sK | sV | sWh[256][36] | sWo[64][36]
// ---------------------------------------------------------------------------
#define SM_K   36864
#define SM_V   73728
#define SM_WH  110592
#define SM_WO  147456
#define SMEMT  156672
#define QSCALE 0.3606737602222409f   /* 0.25 * log2(e) */

__global__ void __launch_bounds__(512, 1) k_fused(
    const float* __restrict__ z, const float* __restrict__ ln_scale,
    const float* __restrict__ ln_bias, const float* __restrict__ bg,
    const float* __restrict__ Wo, const float* __restrict__ bo,
    float* __restrict__ y)
{
    extern __shared__ char sm[];
    uint32_t* sA  = (uint32_t*)sm;               // zn fp16 [256][36w]
    uint32_t* sKp = (uint32_t*)(sm + SM_K);
    uint32_t* sVp = (uint32_t*)(sm + SM_V);
    uint32_t* sWh = (uint32_t*)(sm + SM_WH);
    uint32_t* sWo = (uint32_t*)(sm + SM_WO);
    uint32_t sb;
    asm("{ .reg .u64 t; cvta.to.shared.u64 t, %1; cvt.u32.u64 %0, t; }"
        : "=r"(sb) : "l"(sm));

    const int tid  = threadIdx.x;
    const int base = blockIdx.x * 256;           // global row base (b*L+l)*256

    // ---- stage weights ----
    for (int idx = tid; idx < 8192; idx += 512) {
        int O = idx >> 5, i2 = idx & 31;
        sWh[O*36 + i2] = g_Wh[idx];
    }
    for (int idx = tid; idx < 2048; idx += 512) {
        int n = idx >> 5, i2 = idx & 31;
        float2 wv = *(const float2*)(Wo + n*64 + i2*2);
        sWo[n*36 + i2] = h16x2(wv.y, wv.x);
    }

    // ---- LayerNorm: 2 threads per row (32 channels each) -> sA fp16 ----
    {
        const int r = tid >> 1, q = tid & 1;
        const float* zr = z + (size_t)(base + r)*64 + q*32;
        float4 zv[8];
        #pragma unroll
        for (int f = 0; f < 8; f++) zv[f] = ((const float4*)zr)[f];
        float s = 0.f, ss = 0.f;
        #pragma unroll
        for (int f = 0; f < 8; f++) {
            s  += zv[f].x + zv[f].y + zv[f].z + zv[f].w;
            ss += zv[f].x*zv[f].x + zv[f].y*zv[f].y
                + zv[f].z*zv[f].z + zv[f].w*zv[f].w;
        }
        s  += __shfl_xor_sync(0xffffffffu, s, 1);
        ss += __shfl_xor_sync(0xffffffffu, ss, 1);
        float mu  = s * (1.0f/64.0f);
        float var = ss * (1.0f/64.0f) - mu*mu;
        float rs  = rsqrtf(var + 1e-5f);
        #pragma unroll
        for (int f = 0; f < 8; f++) {
            float4 sc = ((const float4*)(ln_scale + q*32))[f];
            float4 bi = ((const float4*)(ln_bias  + q*32))[f];
            float v0 = (zv[f].x - mu)*rs*sc.x + bi.x;
            float v1 = (zv[f].y - mu)*rs*sc.y + bi.y;
            float v2 = (zv[f].z - mu)*rs*sc.z + bi.z;
            float v3 = (zv[f].w - mu)*rs*sc.w + bi.w;
            sA[r*36 + q*16 + f*2]     = h16x2(v1, v0);
            sA[r*36 + q*16 + f*2 + 1] = h16x2(v3, v2);
        }
    }
    __syncthreads();

    const int w = tid >> 5, lane = tid & 31;
    const int g = lane >> 2, t = lane & 3;
    const int lr = w*16 + g;                     // local rows lr, lr+8
    const int r0 = base + lr;                    // global rows
    const uint32_t frow = (lane & 15);           // ldmatrix row-lane
    const uint32_t fcol = (lane >> 4) << 4;      // +16B for second 8-ch group

    // ---- projections: warp w -> its 16 rows x 256 out channels ----
    uint32_t qa[4][4];    // QK A-frags per head (prescaled)
    uint32_t Gh[4][4];    // gate frags per head (fp16)
    {
        uint32_t af[4][4];
        {
            const int arow  = w*16 + frow;
            #pragma unroll
            for (int kt = 0; kt < 4; kt++)
                LDSM4(af[kt], sb + arow*144 + kt*32 + fcol);
        }

        #pragma unroll
        for (int jp = 0; jp < 16; jp++) {
            float acc[2][4];
            #pragma unroll
            for (int jj = 0; jj < 2; jj++)
                #pragma unroll
                for (int k = 0; k < 4; k++) acc[jj][k] = 0.f;

            const uint32_t wbase = (jp*16 + frow)*144 + fcol;
            #pragma unroll
            for (int kt = 0; kt < 4; kt++) {
                uint32_t wh[4];
                LDSM4(wh, sb + SM_WH + wbase + kt*32);
                uint32_t b0h[2] = {wh[0], wh[2]}, b1h[2] = {wh[1], wh[3]};
                mma_f16(acc[0], af[kt], b0h);
                mma_f16(acc[1], af[kt], b1h);
            }

            #pragma unroll
            for (int jj = 0; jj < 2; jj++) {
                const int j = jp*2 + jj;
                if (j < 8) {                         // Q -> register A-frags
                    const int h = j >> 1, part = j & 1;
                    qa[h][part*2]     = h16x2(QSCALE*acc[jj][1], QSCALE*acc[jj][0]);
                    qa[h][part*2 + 1] = h16x2(QSCALE*acc[jj][3], QSCALE*acc[jj][2]);
                } else if (j < 16) {                 // K -> smem
                    const int jx = j - 8;
                    sKp[lr*36 + jx*4 + t]     = h16x2(acc[jj][1], acc[jj][0]);
                    sKp[(lr+8)*36 + jx*4 + t] = h16x2(acc[jj][3], acc[jj][2]);
                } else if (j < 24) {                 // V -> smem
                    const int jx = j - 16;
                    sVp[lr*36 + jx*4 + t]     = h16x2(acc[jj][1], acc[jj][0]);
                    sVp[(lr+8)*36 + jx*4 + t] = h16x2(acc[jj][3], acc[jj][2]);
                } else {                             // gate -> register frags
                    const int jx = j - 24, h = jx >> 1, part = jx & 1;
                    float2 bg2 = *(const float2*)(bg + jx*8 + 2*t);
                    float g0 = 1.0f/(1.0f + ex2(-1.4426950408889634f*(acc[jj][0] + bg2.x)));
                    float g1 = 1.0f/(1.0f + ex2(-1.4426950408889634f*(acc[jj][1] + bg2.y)));
                    float g2 = 1.0f/(1.0f + ex2(-1.4426950408889634f*(acc[jj][2] + bg2.x)));
                    float g3 = 1.0f/(1.0f + ex2(-1.4426950408889634f*(acc[jj][3] + bg2.y)));
                    Gh[h][part*2]     = h16x2(g1, g0);
                    Gh[h][part*2 + 1] = h16x2(g3, g2);
                }
            }
        }
    }
    __syncthreads();

    // ---- attention main loop (fully unrolled) ----
    float o_[4][2][4];
    float lacc[4][4];
    #pragma unroll
    for (int h = 0; h < 4; h++) {
        #pragma unroll
        for (int k = 0; k < 4; k++) lacc[h][k] = 0.f;
        #pragma unroll
        for (int nt = 0; nt < 2; nt++)
            #pragma unroll
            for (int k = 0; k < 4; k++) o_[h][nt][k] = 0.f;
    }
    const uint32_t bones[2] = {0x3C003C00u, 0x3C003C00u};
    const uint32_t vbase = sb + SM_V + frow*144 + fcol;
    const int krow0 = g*36 + t;

    #pragma unroll
    for (int kb = 0; kb < 16; kb++) {
        #pragma unroll
        for (int h = 0; h < 4; h++) {
            const int hb2 = h * 8;
            uint32_t kf0[2], kf1[2];
            {
                const uint32_t* kp = sKp + (kb*16)*36 + krow0 + hb2;
                kf0[0] = kp[0];        kf0[1] = kp[4];
                kf1[0] = kp[8*36];     kf1[1] = kp[8*36 + 4];
            }
            uint32_t vf[4];
            LDSM4T(vf, vbase + kb*2304 + h*32);

            float s0[4] = {0.f,0.f,0.f,0.f}, s1[4] = {0.f,0.f,0.f,0.f};
            mma_f16(s0, qa[h], kf0);
            mma_f16(s1, qa[h], kf1);
            s0[0] = ex2(s0[0]); s0[1] = ex2(s0[1]);
            s0[2] = ex2(s0[2]); s0[3] = ex2(s0[3]);
            s1[0] = ex2(s1[0]); s1[1] = ex2(s1[1]);
            s1[2] = ex2(s1[2]); s1[3] = ex2(s1[3]);
            uint32_t pa[4];
            pa[0] = h16x2(s0[1], s0[0]);
            pa[1] = h16x2(s0[3], s0[2]);
            pa[2] = h16x2(s1[1], s1[0]);
            pa[3] = h16x2(s1[3], s1[2]);
            mma_f16(lacc[h], pa, bones);        // fp32 row-sum accumulator
            mma_f16(o_[h][0], pa, vf + 0);
            mma_f16(o_[h][1], pa, vf + 2);
        }
    }

    // ---- normalize + gate, pack epilogue A fragments ----
    uint32_t A[4][4];
    #pragma unroll
    for (int h = 0; h < 4; h++) {
        const float inv0 = 1.0f / lacc[h][0];   // row g
        const float inv1 = 1.0f / lacc[h][2];   // row g+8
        #pragma unroll
        for (int nt = 0; nt < 2; nt++) {
            float2 G0 = __half22float2(*(__half2*)&Gh[h][nt*2]);
            float2 G1 = __half22float2(*(__half2*)&Gh[h][nt*2 + 1]);
            float v0 = o_[h][nt][0]*inv0*G0.x;
            float v1 = o_[h][nt][1]*inv0*G0.y;
            float v2 = o_[h][nt][2]*inv1*G1.x;
            float v3 = o_[h][nt][3]*inv1*G1.y;
            A[h][nt*2]     = h16x2(v1, v0);
            A[h][nt*2 + 1] = h16x2(v3, v2);
        }
    }

    // ---- fused output projection (Wo frags via ldmatrix) ----
    #pragma unroll
    for (int jp = 0; jp < 4; jp++) {
        float acc[2][4];
        #pragma unroll
        for (int jj = 0; jj < 2; jj++)
            #pragma unroll
            for (int k = 0; k < 4; k++) acc[jj][k] = 0.f;

        const uint32_t wbase = (jp*16 + frow)*144 + fcol;
        #pragma unroll
        for (int h = 0; h < 4; h++) {
            uint32_t wm[4];
            LDSM4(wm, sb + SM_WO + wbase + h*32);
            uint32_t b0[2] = {wm[0], wm[2]}, b1[2] = {wm[1], wm[3]};
            mma_f16(acc[0], A[h], b0);
            mma_f16(acc[1], A[h], b1);
        }
        #pragma unroll
        for (int jj = 0; jj < 2; jj++) {
            const int c = (jp*2 + jj)*8 + 2*t;
            float2 bo2 = *(const float2*)(bo + c);
            *(float2*)(y + (size_t)r0*64 + c)     = make_float2(acc[jj][0]+bo2.x, acc[jj][1]+bo2.y);
            *(float2*)(y + (size_t)(r0+8)*64 + c) = make_float2(acc[jj][2]+bo2.x, acc[jj][3]+bo2.y);
        }
    }
}

// ---------------------------------------------------------------------------
extern "C" void kernel_launch(void* const* d_in, const int* in_sizes, int n_in,
                              void* d_out, int out_size)
{
    (void)in_sizes; (void)n_in; (void)out_size;
    const float* z  = (const float*)d_in[0];
    const float* ls = (const float*)d_in[1];
    const float* lb = (const float*)d_in[2];
    const float* Wq = (const float*)d_in[3];
    const float* Wk = (const float*)d_in[4];
    const float* Wv = (const float*)d_in[5];
    const float* Wg = (const float*)d_in[6];
    const float* bg = (const float*)d_in[7];
    const float* Wo = (const float*)d_in[8];
    const float* bo = (const float*)d_in[9];
    float* y = (float*)d_out;

    (void)cudaFuncSetAttribute(k_fused, cudaFuncAttributeMaxDynamicSharedMemorySize, SMEMT);

    k_prep<<<32, 256>>>(Wq, Wk, Wv, Wg);
    k_fused<<<BATCH*LEN, 512, SMEMT>>>(z, ls, lb, bg, Wo, bo, y);
}